// round 3
// baseline (speedup 1.0000x reference)
#include <cuda_runtime.h>
#include <math.h>
#include <float.h>
#include <stdint.h>

#define BB 16
#define SS 512
#define DD 512
#define VV 32000
#define KK 4
#define TT 64
#define TOK_SOS 1
#define TOK_EOS 2
#define TOK_PAD 0
#define NEGV (-1e9f)
#define NVB 63           /* ceil(32000/512) column blocks */
#define NROWS 64

#define NEGINF __int_as_float(0xff800000)

/* ------------------------------------------------------------------ */
/* Device state (__device__ globals; no allocations allowed)           */
/* ------------------------------------------------------------------ */
__device__ float g_Wqk[DD * DD];            /* W_q @ W_k^T              */
__device__ float g_he[NROWS * DD];          /* e rows (row-major)       */
__device__ float g_q[NROWS * DD];           /* q' = e @ Wqk             */
__device__ float g_hT[DD * NROWS];          /* h = e+ctx, TRANSPOSED    */
__device__ float g_pval[NROWS * 64 * 4];    /* per-block top4 logits    */
__device__ int   g_pidx[NROWS * 64 * 4];    /* per-block top4 token ids */
__device__ float g_pmax[NROWS * 64];        /* per-block row max        */
__device__ float g_psum[NROWS * 64];        /* per-block sum exp(l-max) */
__device__ float g_cand_lp[NROWS * KK];     /* per-row top4 logp        */
__device__ int   g_cand_v[NROWS * KK];      /* per-row top4 tokens      */
__device__ float g_scores[NROWS];
__device__ int   g_fin[NROWS];
__device__ int   g_seqs[BB * KK * TT];
__device__ int   g_last[NROWS];

/* ------------------------------------------------------------------ */
/* Warp helpers                                                        */
/* ------------------------------------------------------------------ */
static __device__ __forceinline__ float warpMaxf(float v) {
#pragma unroll
    for (int o = 16; o > 0; o >>= 1) v = fmaxf(v, __shfl_xor_sync(0xffffffffu, v, o));
    return v;
}
static __device__ __forceinline__ float warpSumf(float v) {
#pragma unroll
    for (int o = 16; o > 0; o >>= 1) v += __shfl_xor_sync(0xffffffffu, v, o);
    return v;
}
/* argmax, ties -> lower index (jax.lax.top_k semantics) */
static __device__ __forceinline__ void warpArgMax(float& v, int& i) {
#pragma unroll
    for (int o = 16; o > 0; o >>= 1) {
        float ov = __shfl_xor_sync(0xffffffffu, v, o);
        int   oi = __shfl_xor_sync(0xffffffffu, i, o);
        if (ov > v || (ov == v && oi < i)) { v = ov; i = oi; }
    }
}

/* ------------------------------------------------------------------ */
/* kWqk: Wqk = W_q @ W_k^T (once per launch)                           */
/* ------------------------------------------------------------------ */
__global__ void __launch_bounds__(256) kWqk(const float* __restrict__ Wq,
                                            const float* __restrict__ Wk) {
    __shared__ float As[16][16];
    __shared__ float Bs[16][17];
    int tx = threadIdx.x, ty = threadIdx.y;
    int d1 = blockIdx.y * 16 + ty;
    int d2 = blockIdx.x * 16 + tx;
    float acc = 0.f;
    for (int e0 = 0; e0 < DD; e0 += 16) {
        As[ty][tx] = Wq[d1 * DD + e0 + tx];
        Bs[ty][tx] = Wk[(blockIdx.x * 16 + ty) * DD + e0 + tx];
        __syncthreads();
#pragma unroll
        for (int i = 0; i < 16; i++) acc = fmaf(As[ty][i], Bs[tx][i], acc);
        __syncthreads();
    }
    g_Wqk[d1 * DD + d2] = acc;
}

__global__ void kInit() {
    int tid = threadIdx.x;
    if (tid < BB) g_last[tid] = TOK_SOS;
}

/* ------------------------------------------------------------------ */
/* kA: e = emb[last]; q' = e @ Wqk.  4 rows per block, 256 threads.    */
/* ------------------------------------------------------------------ */
__global__ void __launch_bounds__(256) kA(const float* __restrict__ emb, int M) {
    __shared__ float es[4][DD];
    int tid = threadIdx.x;
    int r0 = blockIdx.x * 4;
    for (int rr = 0; rr < 4; rr++) {
        int row = r0 + rr;
        if (row < M) {
            int tok = g_last[row];
            const float* er = emb + (size_t)tok * DD;
            for (int d = tid; d < DD; d += 256) {
                float v = er[d];
                es[rr][d] = v;
                g_he[row * DD + d] = v;
            }
        } else {
            for (int d = tid; d < DD; d += 256) es[rr][d] = 0.f;
        }
    }
    __syncthreads();
    float a0[4] = {0, 0, 0, 0}, a1[4] = {0, 0, 0, 0};
#pragma unroll 4
    for (int d = 0; d < DD; d++) {
        float w0 = g_Wqk[d * DD + tid];
        float w1 = g_Wqk[d * DD + tid + 256];
#pragma unroll
        for (int rr = 0; rr < 4; rr++) {
            float e = es[rr][d];
            a0[rr] = fmaf(e, w0, a0[rr]);
            a1[rr] = fmaf(e, w1, a1[rr]);
        }
    }
    for (int rr = 0; rr < 4; rr++) {
        int row = r0 + rr;
        if (row < M) {
            g_q[row * DD + tid]       = a0[rr];
            g_q[row * DD + tid + 256] = a1[rr];
        }
    }
}

/* ------------------------------------------------------------------ */
/* kATT: masked softmax attention; writes h TRANSPOSED to g_hT.        */
/* One block per row.                                                  */
/* ------------------------------------------------------------------ */
__global__ void __launch_bounds__(256) kATT(const float* __restrict__ enc,
                                            const int* __restrict__ lens, int kpb) {
    __shared__ __align__(16) float qs[DD];
    __shared__ float as[SS];
    __shared__ float red1[8], red2[8];
    int tid = threadIdx.x, warp = tid >> 5, lane = tid & 31;
    int row = blockIdx.x;
    int b = row / kpb;
    int len = lens[b];
    qs[tid]       = g_q[row * DD + tid];
    qs[tid + 256] = g_q[row * DD + tid + 256];
    __syncthreads();
    const float scl = 1.0f / sqrtf(512.0f);
    /* scores */
    for (int s = warp; s < SS; s += 8) {
        const float4* er = (const float4*)(enc + ((size_t)b * SS + s) * DD);
        const float4* qr = (const float4*)qs;
        float sum = 0.f;
#pragma unroll
        for (int i = 0; i < 4; i++) {
            float4 e4 = er[lane + 32 * i];
            float4 q4 = qr[lane + 32 * i];
            sum += e4.x * q4.x + e4.y * q4.y + e4.z * q4.z + e4.w * q4.w;
        }
        sum = warpSumf(sum);
        if (lane == 0) as[s] = (s < len) ? sum * scl : NEGV;
    }
    __syncthreads();
    /* softmax */
    float m = -FLT_MAX;
    for (int s = tid; s < SS; s += 256) m = fmaxf(m, as[s]);
    m = warpMaxf(m);
    if (lane == 0) red1[warp] = m;
    __syncthreads();
    if (tid == 0) {
        float mm = red1[0];
        for (int i = 1; i < 8; i++) mm = fmaxf(mm, red1[i]);
        red1[0] = mm;
    }
    __syncthreads();
    m = red1[0];
    float ps = 0.f;
    for (int s = tid; s < SS; s += 256) {
        float p = expf(as[s] - m);   /* masked entries: expf(-1e9-m) == 0 exactly */
        as[s] = p;
        ps += p;
    }
    ps = warpSumf(ps);
    if (lane == 0) red2[warp] = ps;
    __syncthreads();
    if (tid == 0) {
        float t = 0.f;
        for (int i = 0; i < 8; i++) t += red2[i];
        red2[0] = t;
    }
    __syncthreads();
    float inv = 1.0f / red2[0];
    /* ctx (coalesced across threads for each s) */
    int d0 = tid, d1 = tid + 256;
    float c0 = 0.f, c1 = 0.f;
    for (int s = 0; s < len; s++) {
        float p = as[s];
        const float* er = enc + ((size_t)b * SS + s) * DD;
        c0 = fmaf(p, er[d0], c0);
        c1 = fmaf(p, er[d1], c1);
    }
    g_hT[d0 * NROWS + row] = g_he[row * DD + d0] + c0 * inv;
    g_hT[d1 * NROWS + row] = g_he[row * DD + d1] + c1 * inv;
}

/* ------------------------------------------------------------------ */
/* kB: logits = h @ W_fc + b_fc, fused per-block top4 + lse partials.  */
/* Tile: 512 cols x 32 rows, 256 threads (2 cols each).                */
/* Inner loop: fma.rn.f32x2 packing TWO ROWS per instruction.          */
/* Dynamic smem 64KB, reused for h^T staging then logits.              */
/* ------------------------------------------------------------------ */
__global__ void __launch_bounds__(256) kB(const float* __restrict__ Wfc,
                                          const float* __restrict__ bfc, int M) {
    extern __shared__ __align__(16) float sm[];   /* 16384 floats = 64KB */
    int tid = threadIdx.x;
    int rbase = blockIdx.y * 32;
    int vbase = blockIdx.x * 512;
    /* stage h transposed: sm[d*32+r]; coalesced (g_hT is [d][row]) */
    for (int i = tid; i < 32 * DD; i += 256) {
        int d = i >> 5;
        int r = i & 31;
        int row = rbase + r;
        sm[i] = (row < M) ? g_hT[d * NROWS + row] : 0.f;
    }
    __syncthreads();
    int v0 = vbase + 2 * tid;
    bool valid = v0 < VV;
    int vc = valid ? v0 : (VV - 2);
    const float* wp = Wfc + vc;
    unsigned long long acc0[16], acc1[16];
#pragma unroll
    for (int j = 0; j < 16; j++) { acc0[j] = 0ull; acc1[j] = 0ull; }
#pragma unroll 4
    for (int d = 0; d < DD; d++) {
        float2 w = *(const float2*)(wp + (size_t)d * VV);
        unsigned long long wxx, wyy;
        unsigned int wxi = __float_as_uint(w.x), wyi = __float_as_uint(w.y);
        asm("mov.b64 %0,{%1,%1};" : "=l"(wxx) : "r"(wxi));
        asm("mov.b64 %0,{%1,%1};" : "=l"(wyy) : "r"(wyi));
        const unsigned long long* hp = (const unsigned long long*)(sm + d * 32);
#pragma unroll
        for (int j = 0; j < 16; j++) {
            unsigned long long h2 = hp[j];    /* rows 2j, 2j+1 (LDS.64 broadcast) */
            asm("fma.rn.f32x2 %0,%1,%2,%3;" : "=l"(acc0[j]) : "l"(h2), "l"(wxx), "l"(acc0[j]));
            asm("fma.rn.f32x2 %0,%1,%2,%3;" : "=l"(acc1[j]) : "l"(h2), "l"(wyy), "l"(acc1[j]));
        }
    }
    __syncthreads();
    /* write logits (+bias) into sm as [32 rows][512 cols] */
    float bx = bfc[vc], by = bfc[vc + 1];
    int c0 = 2 * tid, c1 = 2 * tid + 1;
#pragma unroll
    for (int j = 0; j < 16; j++) {
        unsigned int lo, hi;
        asm("mov.b64 {%0,%1},%2;" : "=r"(lo), "=r"(hi) : "l"(acc0[j]));
        float l0 = __uint_as_float(lo) + bx;    /* row 2j,   col c0 */
        float l1 = __uint_as_float(hi) + bx;    /* row 2j+1, col c0 */
        asm("mov.b64 {%0,%1},%2;" : "=r"(lo), "=r"(hi) : "l"(acc1[j]));
        float m0 = __uint_as_float(lo) + by;
        float m1 = __uint_as_float(hi) + by;
        if (!valid) { l0 = l1 = m0 = m1 = NEGINF; }
        sm[(2 * j) * 512 + c0]     = l0;
        sm[(2 * j + 1) * 512 + c0] = l1;
        sm[(2 * j) * 512 + c1]     = m0;
        sm[(2 * j + 1) * 512 + c1] = m1;
    }
    __syncthreads();
    /* per-row max / sumexp / top4.  Warp w handles rows w*4..w*4+3. */
    int warp = tid >> 5, lane = tid & 31;
    for (int rr = 0; rr < 4; rr++) {
        int r = warp * 4 + rr;
        float* rowp = sm + r * 512;
        float m = NEGINF;
        for (int c = lane; c < 512; c += 32) m = fmaxf(m, rowp[c]);
        m = warpMaxf(m);
        float s = 0.f;
        for (int c = lane; c < 512; c += 32) s += expf(rowp[c] - m);
        s = warpSumf(s);
        int gr = rbase + r;
        int base = (gr * 64 + blockIdx.x) * 4;
        for (int j = 0; j < 4; j++) {
            float bv = NEGINF;
            int bc = 0x7fffffff;
            for (int c = lane; c < 512; c += 32) {
                float v = rowp[c];
                if (v > bv || (v == bv && c < bc)) { bv = v; bc = c; }
            }
            warpArgMax(bv, bc);
            if (lane == 0) { g_pval[base + j] = bv; g_pidx[base + j] = vbase + bc; }
            if (bc < 0x7fffffff && (bc & 31) == lane) rowp[bc] = NEGINF;
            __syncwarp();
        }
        if (lane == 0) { g_pmax[gr * 64 + blockIdx.x] = m; g_psum[gr * 64 + blockIdx.x] = s; }
    }
}

/* ------------------------------------------------------------------ */
/* kRed: per row, merge 63 block-partials -> lse + global top4 logp.   */
/* ------------------------------------------------------------------ */
__global__ void __launch_bounds__(256) kRed() {
    int row = blockIdx.x;
    int tid = threadIdx.x;
    __shared__ float sv[256];
    __shared__ float rv[256];
    __shared__ int   ri[256];
    __shared__ int   rs[256];
    /* global max */
    float pm = (tid < NVB) ? g_pmax[row * 64 + tid] : NEGINF;
    sv[tid] = pm;
    __syncthreads();
    for (int o = 128; o > 0; o >>= 1) {
        if (tid < o) sv[tid] = fmaxf(sv[tid], sv[tid + o]);
        __syncthreads();
    }
    float gmax = sv[0];
    __syncthreads();
    /* global sumexp */
    float sc = (tid < NVB) ? g_psum[row * 64 + tid] * expf(pm - gmax) : 0.f;
    sv[tid] = sc;
    __syncthreads();
    for (int o = 128; o > 0; o >>= 1) {
        if (tid < o) sv[tid] += sv[tid + o];
        __syncthreads();
    }
    float lse = gmax + logf(sv[0]);
    __syncthreads();
    /* top4 over 252 candidates */
    float cv;
    int ci;
    if (tid < NVB * 4) { cv = g_pval[row * 256 + tid]; ci = g_pidx[row * 256 + tid]; }
    else               { cv = NEGINF;                  ci = 0x7fffffff; }
    for (int j = 0; j < 4; j++) {
        rv[tid] = cv; ri[tid] = ci; rs[tid] = tid;
        __syncthreads();
        for (int o = 128; o > 0; o >>= 1) {
            if (tid < o) {
                float ov = rv[tid + o];
                int oi = ri[tid + o];
                if (ov > rv[tid] || (ov == rv[tid] && oi < ri[tid])) {
                    rv[tid] = ov; ri[tid] = oi; rs[tid] = rs[tid + o];
                }
            }
            __syncthreads();
        }
        if (tid == 0) {
            g_cand_lp[row * 4 + j] = rv[0] - lse;
            g_cand_v[row * 4 + j]  = ri[0];
        }
        int win = rs[0];
        __syncthreads();
        if (tid == win) cv = NEGINF;
    }
}

/* ------------------------------------------------------------------ */
/* kC1: expand SOS into top-K beams (step 1)                           */
/* ------------------------------------------------------------------ */
__global__ void __launch_bounds__(256) kC1() {
    int tid = threadIdx.x;
    for (int i = tid; i < BB * KK * TT; i += 256) {
        int pos = i & 63;
        int r = i >> 6;          /* b*4+k */
        int b = r >> 2, k = r & 3;
        int tok1 = g_cand_v[b * 4 + k];   /* step1 cand rows are indexed by b */
        int v = (pos == 0) ? TOK_SOS : ((pos == 1) ? tok1 : TOK_PAD);
        g_seqs[i] = v;
    }
    if (tid < 64) {
        int b = tid >> 2, k = tid & 3;
        float sc = g_cand_lp[b * 4 + k];
        int tok = g_cand_v[b * 4 + k];
        g_scores[tid] = sc;
        g_fin[tid] = (tok == TOK_EOS) ? 1 : 0;
        g_last[tid] = tok;
    }
}

/* ------------------------------------------------------------------ */
/* kC: beam combine at step t (t >= 2)                                 */
/* ------------------------------------------------------------------ */
__global__ void __launch_bounds__(256) kC(int t) {
    __shared__ int sseq[BB * KK * TT];   /* 16KB */
    __shared__ float snsc[64];
    __shared__ int sbid[64];
    __shared__ int stok[64];
    __shared__ int snfin[64];
    int tid = threadIdx.x;
    for (int i = tid; i < BB * KK * TT; i += 256) sseq[i] = g_seqs[i];
    __syncthreads();
    if (tid < BB) {
        int b = tid;
        float tot[16];
        int tk[16];
        for (int k = 0; k < KK; k++) {
            int r = b * 4 + k;
            float sc = g_scores[r];
            int f = g_fin[r];
            for (int j = 0; j < KK; j++) {
                float lp = f ? ((j == 0) ? 0.f : NEGV) : g_cand_lp[r * 4 + j];
                tot[k * 4 + j] = sc + lp;
                tk[k * 4 + j] = f ? TOK_PAD : g_cand_v[r * 4 + j];
            }
        }
        for (int j = 0; j < KK; j++) {
            float bv = -FLT_MAX;
            int bi = 0;
            for (int c = 0; c < 16; c++)
                if (tot[c] > bv) { bv = tot[c]; bi = c; }   /* strict > => lowest idx on tie */
            snsc[b * 4 + j] = bv;
            sbid[b * 4 + j] = bi >> 2;
            stok[b * 4 + j] = tk[bi];
            tot[bi] = -FLT_MAX;
        }
    }
    __syncthreads();
    if (tid < 64) {
        int b = tid >> 2;
        snfin[tid] = g_fin[b * 4 + sbid[tid]] | ((stok[tid] == TOK_EOS) ? 1 : 0);
    }
    __syncthreads();
    if (tid < 64) {
        g_scores[tid] = snsc[tid];
        g_fin[tid] = snfin[tid];
        g_last[tid] = stok[tid];
    }
    for (int i = tid; i < BB * KK * TT; i += 256) {
        int b = i >> 8;
        int k = (i >> 6) & 3;
        int pos = i & 63;
        int src = sseq[b * 256 + sbid[b * 4 + k] * 64 + pos];
        g_seqs[i] = (pos == t) ? stok[b * 4 + k] : src;
    }
}

/* ------------------------------------------------------------------ */
/* kOut: pick best beam, write output                                  */
/* ------------------------------------------------------------------ */
__global__ void __launch_bounds__(64) kOut(float* out, int out_size) {
    __shared__ int best[16];
    int tid = threadIdx.x;
    if (tid < 16) {
        float bv = -FLT_MAX;
        int bi = 0;
        for (int k = 0; k < 4; k++) {
            float s = g_scores[tid * 4 + k];
            if (s > bv) { bv = s; bi = k; }   /* argmax: first max wins */
        }
        best[tid] = bi;
        if (out_size >= 1040) out[1024 + tid] = bv;
        else if (out_size < 1024 && out_size >= 16) out[tid] = bv;
    }
    __syncthreads();
    if (out_size >= 1024) {
        for (int i = tid; i < 1024; i += 64) {
            int b = i >> 6, pos = i & 63;
            out[i] = (float)g_seqs[b * 256 + best[b] * 64 + pos];
        }
    }
}

/* ------------------------------------------------------------------ */
extern "C" void kernel_launch(void* const* d_in, const int* in_sizes, int n_in,
                              void* d_out, int out_size) {
    const float* enc  = (const float*)d_in[0];
    const int*   lens = (const int*)d_in[1];
    const float* emb  = (const float*)d_in[2];
    const float* Wq   = (const float*)d_in[3];
    const float* Wk   = (const float*)d_in[4];
    const float* Wfc  = (const float*)d_in[5];
    const float* bfc  = (const float*)d_in[6];
    float* out = (float*)d_out;

    cudaFuncSetAttribute(kB, cudaFuncAttributeMaxDynamicSharedMemorySize, 65536);

    kWqk<<<dim3(32, 32), dim3(16, 16)>>>(Wq, Wk);
    kInit<<<1, 32>>>();

    /* step 1: decode from SOS, rows = batch index (M=16) */
    kA<<<4, 256>>>(emb, 16);
    kATT<<<16, 256>>>(enc, lens, 1);
    kB<<<dim3(NVB, 1), 256, 65536>>>(Wfc, bfc, 16);
    kRed<<<16, 256>>>();
    kC1<<<1, 256>>>();

    /* steps 2..63: rows = b*4+k (M=64) */
    for (int t = 2; t < TT; t++) {
        kA<<<16, 256>>>(emb, 64);
        kATT<<<64, 256>>>(enc, lens, 4);
        kB<<<dim3(NVB, 2), 256, 65536>>>(Wfc, bfc, 64);
        kRed<<<64, 256>>>();
        kC<<<1, 256>>>(t);
    }

    kOut<<<1, 64>>>(out, out_size);
}

// round 15
// speedup vs baseline: 1.2327x; 1.2327x over previous
#include <cuda_runtime.h>
#include <math.h>
#include <float.h>
#include <stdint.h>

#define BB 16
#define SS 512
#define DD 512
#define VV 32000
#define KK 4
#define TT 64
#define TOK_SOS 1
#define TOK_EOS 2
#define TOK_PAD 0
#define NEGV (-1e9f)
#define NVB 63           /* ceil(32000/512) column blocks */
#define NROWS 64

#define NEGINF __int_as_float(0xff800000)

/* ------------------------------------------------------------------ */
/* Device state (__device__ globals; no allocations allowed)           */
/* ------------------------------------------------------------------ */
__device__ float g_Wqk[DD * DD];            /* W_q @ W_k^T              */
__device__ float g_hT[DD * NROWS];          /* h = e+ctx, TRANSPOSED    */
__device__ float g_pval[NROWS * 64 * 4];    /* per-block top4 logits    */
__device__ int   g_pidx[NROWS * 64 * 4];    /* per-block top4 token ids */
__device__ float g_pmax[NROWS * 64];        /* per-block row max        */
__device__ float g_psum[NROWS * 64];        /* per-block sum exp(l-max) */
__device__ float g_scores[NROWS];
__device__ int   g_fin[NROWS];
__device__ int   g_seqs[BB * KK * TT];
__device__ int   g_last[NROWS];

/* ------------------------------------------------------------------ */
/* Warp helpers                                                        */
/* ------------------------------------------------------------------ */
static __device__ __forceinline__ float warpMaxf(float v) {
#pragma unroll
    for (int o = 16; o > 0; o >>= 1) v = fmaxf(v, __shfl_xor_sync(0xffffffffu, v, o));
    return v;
}
static __device__ __forceinline__ float warpSumf(float v) {
#pragma unroll
    for (int o = 16; o > 0; o >>= 1) v += __shfl_xor_sync(0xffffffffu, v, o);
    return v;
}
/* argmax, ties -> lower index (jax.lax.top_k semantics) */
static __device__ __forceinline__ void warpArgMax(float& v, int& i) {
#pragma unroll
    for (int o = 16; o > 0; o >>= 1) {
        float ov = __shfl_xor_sync(0xffffffffu, v, o);
        int   oi = __shfl_xor_sync(0xffffffffu, i, o);
        if (ov > v || (ov == v && oi < i)) { v = ov; i = oi; }
    }
}

/* ------------------------------------------------------------------ */
/* kWqk: Wqk = W_q @ W_k^T (once per launch)                           */
/* ------------------------------------------------------------------ */
__global__ void __launch_bounds__(256) kWqk(const float* __restrict__ Wq,
                                            const float* __restrict__ Wk) {
    __shared__ float As[16][16];
    __shared__ float Bs[16][17];
    int tx = threadIdx.x, ty = threadIdx.y;
    int d1 = blockIdx.y * 16 + ty;
    int d2 = blockIdx.x * 16 + tx;
    float acc = 0.f;
    for (int e0 = 0; e0 < DD; e0 += 16) {
        As[ty][tx] = Wq[d1 * DD + e0 + tx];
        Bs[ty][tx] = Wk[(blockIdx.x * 16 + ty) * DD + e0 + tx];
        __syncthreads();
#pragma unroll
        for (int i = 0; i < 16; i++) acc = fmaf(As[ty][i], Bs[tx][i], acc);
        __syncthreads();
    }
    g_Wqk[d1 * DD + d2] = acc;
}

__global__ void kInit() {
    int tid = threadIdx.x;
    if (tid < BB) g_last[tid] = TOK_SOS;
}

/* ------------------------------------------------------------------ */
/* kQATT: fused e-lookup + q = e@Wqk + masked softmax attention.       */
/* One block per row, 256 threads. Writes h transposed to g_hT.        */
/* ------------------------------------------------------------------ */
__global__ void __launch_bounds__(256) kQATT(const float* __restrict__ enc,
                                             const int* __restrict__ lens,
                                             const float* __restrict__ emb,
                                             int M, int kpb) {
    __shared__ __align__(16) float es[DD];
    __shared__ __align__(16) float qs[DD];
    __shared__ float as[SS];
    __shared__ float red1[8], red2[8];
    int tid = threadIdx.x, warp = tid >> 5, lane = tid & 31;
    int row = blockIdx.x;
    int b = row / kpb;
    int len = lens[b];
    int d0 = tid, d1 = tid + 256;

    /* load embedding row to smem */
    {
        int tok = g_last[row];
        const float* er = emb + (size_t)tok * DD;
        es[d0] = er[d0];
        es[d1] = er[d1];
    }
    __syncthreads();

    /* q = e @ Wqk  (each thread owns cols d0, d1) */
    {
        float q0 = 0.f, q1 = 0.f;
        const float* wq = g_Wqk;
#pragma unroll 8
        for (int dd = 0; dd < DD; dd++) {
            float e = es[dd];
            q0 = fmaf(e, wq[dd * DD + d0], q0);
            q1 = fmaf(e, wq[dd * DD + d1], q1);
        }
        qs[d0] = q0;
        qs[d1] = q1;
    }
    __syncthreads();

    /* scores: preload q into registers, 2 s per pass for ILP */
    {
        const float4* qr = (const float4*)qs;
        float4 q4[4];
#pragma unroll
        for (int i = 0; i < 4; i++) q4[i] = qr[lane + 32 * i];
        const float scl = 1.0f / sqrtf(512.0f);
        const float* ep = enc + (size_t)b * SS * DD;
        for (int s = warp * 64; s < warp * 64 + 64; s += 2) {
            const float4* e0 = (const float4*)(ep + (size_t)s * DD);
            const float4* e1 = (const float4*)(ep + (size_t)(s + 1) * DD);
            float sa = 0.f, sb = 0.f;
#pragma unroll
            for (int i = 0; i < 4; i++) {
                float4 a4 = e0[lane + 32 * i];
                float4 b4 = e1[lane + 32 * i];
                sa = fmaf(a4.x, q4[i].x, sa); sa = fmaf(a4.y, q4[i].y, sa);
                sa = fmaf(a4.z, q4[i].z, sa); sa = fmaf(a4.w, q4[i].w, sa);
                sb = fmaf(b4.x, q4[i].x, sb); sb = fmaf(b4.y, q4[i].y, sb);
                sb = fmaf(b4.z, q4[i].z, sb); sb = fmaf(b4.w, q4[i].w, sb);
            }
            sa = warpSumf(sa);
            sb = warpSumf(sb);
            if (lane == 0) {
                as[s]     = (s < len)     ? sa * scl : NEGV;
                as[s + 1] = (s + 1 < len) ? sb * scl : NEGV;
            }
        }
    }
    __syncthreads();

    /* softmax over as[] */
    float m = -FLT_MAX;
    for (int s = tid; s < SS; s += 256) m = fmaxf(m, as[s]);
    m = warpMaxf(m);
    if (lane == 0) red1[warp] = m;
    __syncthreads();
    if (tid == 0) {
        float mm = red1[0];
        for (int i = 1; i < 8; i++) mm = fmaxf(mm, red1[i]);
        red1[0] = mm;
    }
    __syncthreads();
    m = red1[0];
    float ps = 0.f;
    for (int s = tid; s < SS; s += 256) {
        float p = expf(as[s] - m);   /* masked entries: expf(-1e9-m) == 0 exactly */
        as[s] = p;
        ps += p;
    }
    ps = warpSumf(ps);
    if (lane == 0) red2[warp] = ps;
    __syncthreads();
    if (tid == 0) {
        float t = 0.f;
        for (int i = 0; i < 8; i++) t += red2[i];
        red2[0] = t;
    }
    __syncthreads();
    float inv = 1.0f / red2[0];

    /* ctx: fixed 512 iterations (p==0 exactly beyond len), deep unroll
       for memory-level parallelism against L2 latency */
    {
        float c0 = 0.f, c1 = 0.f;
        const float* ep = enc + (size_t)b * SS * DD;
#pragma unroll 8
        for (int s = 0; s < SS; s++) {
            float p = as[s];
            c0 = fmaf(p, ep[(size_t)s * DD + d0], c0);
            c1 = fmaf(p, ep[(size_t)s * DD + d1], c1);
        }
        g_hT[d0 * NROWS + row] = es[d0] + c0 * inv;
        g_hT[d1 * NROWS + row] = es[d1] + c1 * inv;
    }
}

/* ------------------------------------------------------------------ */
/* kB: logits = h @ W_fc + b_fc, fused per-block top4 + lse partials.  */
/* Tile: 512 cols x 32 rows, 256 threads (2 cols each).                */
/* Inner loop: fma.rn.f32x2, TWO ROWS per instruction; h via LDS.128.  */
/* ------------------------------------------------------------------ */
__global__ void __launch_bounds__(256) kB(const float* __restrict__ Wfc,
                                          const float* __restrict__ bfc, int M) {
    extern __shared__ __align__(16) float sm[];   /* 16384 floats = 64KB */
    int tid = threadIdx.x;
    int rbase = blockIdx.y * 32;
    int vbase = blockIdx.x * 512;
    /* stage h transposed: sm[d*32+r]; coalesced (g_hT is [d][row]) */
    for (int i = tid; i < 32 * DD; i += 256) {
        int d = i >> 5;
        int r = i & 31;
        int row = rbase + r;
        sm[i] = (row < M) ? g_hT[d * NROWS + row] : 0.f;
    }
    __syncthreads();
    int v0 = vbase + 2 * tid;
    bool valid = v0 < VV;
    int vc = valid ? v0 : (VV - 2);
    const float* wp = Wfc + vc;
    unsigned long long acc0[16], acc1[16];
#pragma unroll
    for (int j = 0; j < 16; j++) { acc0[j] = 0ull; acc1[j] = 0ull; }
#pragma unroll 4
    for (int d = 0; d < DD; d++) {
        float2 w = *(const float2*)(wp + (size_t)d * VV);
        unsigned long long wxx, wyy;
        unsigned int wxi = __float_as_uint(w.x), wyi = __float_as_uint(w.y);
        asm("mov.b64 %0,{%1,%1};" : "=l"(wxx) : "r"(wxi));
        asm("mov.b64 %0,{%1,%1};" : "=l"(wyy) : "r"(wyi));
        const ulonglong2* hp = (const ulonglong2*)(sm + d * 32);
#pragma unroll
        for (int j = 0; j < 8; j++) {
            ulonglong2 h4 = hp[j];            /* rows 4j..4j+3 via LDS.128 bcast */
            asm("fma.rn.f32x2 %0,%1,%2,%3;" : "=l"(acc0[2 * j])     : "l"(h4.x), "l"(wxx), "l"(acc0[2 * j]));
            asm("fma.rn.f32x2 %0,%1,%2,%3;" : "=l"(acc1[2 * j])     : "l"(h4.x), "l"(wyy), "l"(acc1[2 * j]));
            asm("fma.rn.f32x2 %0,%1,%2,%3;" : "=l"(acc0[2 * j + 1]) : "l"(h4.y), "l"(wxx), "l"(acc0[2 * j + 1]));
            asm("fma.rn.f32x2 %0,%1,%2,%3;" : "=l"(acc1[2 * j + 1]) : "l"(h4.y), "l"(wyy), "l"(acc1[2 * j + 1]));
        }
    }
    __syncthreads();
    /* write logits (+bias) into sm as [32 rows][512 cols] */
    float bx = bfc[vc], by = bfc[vc + 1];
    int c0 = 2 * tid, c1 = 2 * tid + 1;
#pragma unroll
    for (int j = 0; j < 16; j++) {
        unsigned int lo, hi;
        asm("mov.b64 {%0,%1},%2;" : "=r"(lo), "=r"(hi) : "l"(acc0[j]));
        float l0 = __uint_as_float(lo) + bx;    /* row 2j,   col c0 */
        float l1 = __uint_as_float(hi) + bx;    /* row 2j+1, col c0 */
        asm("mov.b64 {%0,%1},%2;" : "=r"(lo), "=r"(hi) : "l"(acc1[j]));
        float m0 = __uint_as_float(lo) + by;
        float m1 = __uint_as_float(hi) + by;
        if (!valid) { l0 = l1 = m0 = m1 = NEGINF; }
        sm[(2 * j) * 512 + c0]     = l0;
        sm[(2 * j + 1) * 512 + c0] = l1;
        sm[(2 * j) * 512 + c1]     = m0;
        sm[(2 * j + 1) * 512 + c1] = m1;
    }
    __syncthreads();
    /* per-row max / sumexp / top4.  Warp w handles rows w*4..w*4+3. */
    int warp = tid >> 5, lane = tid & 31;
    for (int rr = 0; rr < 4; rr++) {
        int r = warp * 4 + rr;
        float* rowp = sm + r * 512;
        float m = NEGINF;
        for (int c = lane; c < 512; c += 32) m = fmaxf(m, rowp[c]);
        m = warpMaxf(m);
        float s = 0.f;
        for (int c = lane; c < 512; c += 32) s += expf(rowp[c] - m);
        s = warpSumf(s);
        int gr = rbase + r;
        int base = (gr * 64 + blockIdx.x) * 4;
        for (int j = 0; j < 4; j++) {
            float bv = NEGINF;
            int bc = 0x7fffffff;
            for (int c = lane; c < 512; c += 32) {
                float v = rowp[c];
                if (v > bv || (v == bv && c < bc)) { bv = v; bc = c; }
            }
            warpArgMax(bv, bc);
            if (lane == 0) { g_pval[base + j] = bv; g_pidx[base + j] = vbase + bc; }
            if (bc < 0x7fffffff && (bc & 31) == lane) rowp[bc] = NEGINF;
            __syncwarp();
        }
        if (lane == 0) { g_pmax[gr * 64 + blockIdx.x] = m; g_psum[gr * 64 + blockIdx.x] = s; }
    }
}

/* ------------------------------------------------------------------ */
/* kFin: fused partial-merge (per-row lse + global top4) + beam        */
/* combine. Single block, 512 threads. t==1 -> SOS expansion.          */
/* ------------------------------------------------------------------ */
__global__ void __launch_bounds__(512) kFin(int t, int M) {
    __shared__ float s_lp[NROWS * KK];
    __shared__ int   s_v[NROWS * KK];
    __shared__ int   sseq[BB * KK * TT];   /* 16KB */
    __shared__ float snsc[64];
    __shared__ int   sbid[64];
    __shared__ int   stok[64];
    __shared__ int   snfin[64];
    int tid = threadIdx.x, warp = tid >> 5, lane = tid & 31;

    /* ---- Part A: per-row merge of 63 block partials ---- */
    for (int row = warp; row < M; row += 16) {
        /* lse over 63 blocks (2 per lane) */
        float pm1 = (lane < NVB) ? g_pmax[row * 64 + lane] : NEGINF;
        float pm2 = (lane + 32 < NVB) ? g_pmax[row * 64 + lane + 32] : NEGINF;
        float gm = warpMaxf(fmaxf(pm1, pm2));
        float s1 = (lane < NVB) ? g_psum[row * 64 + lane] * expf(pm1 - gm) : 0.f;
        float s2 = (lane + 32 < NVB) ? g_psum[row * 64 + lane + 32] * expf(pm2 - gm) : 0.f;
        float lse = gm + logf(warpSumf(s1 + s2));
        /* top4 over 252 candidates (8 per lane, ties -> lower token id) */
        float v[8];
        int ix[8];
#pragma unroll
        for (int j = 0; j < 8; j++) {
            int c = lane * 8 + j;
            if (c < NVB * 4) { v[j] = g_pval[row * 256 + c]; ix[j] = g_pidx[row * 256 + c]; }
            else             { v[j] = NEGINF;                ix[j] = 0x7fffffff; }
        }
        for (int sel = 0; sel < 4; sel++) {
            float bv = NEGINF;
            int bi = 0x7fffffff, bj = -1;
#pragma unroll
            for (int j = 0; j < 8; j++) {
                if (v[j] > bv || (v[j] == bv && ix[j] < bi)) { bv = v[j]; bi = ix[j]; bj = j; }
            }
            float wv = bv;
            int wi = bi;
            warpArgMax(wv, wi);
            if (lane == 0) { s_lp[row * 4 + sel] = wv - lse; s_v[row * 4 + sel] = wi; }
            if (bj >= 0 && wi == bi && wv == bv) v[bj] = NEGINF;  /* token ids unique */
            __syncwarp();
        }
    }
    __syncthreads();

    /* ---- Part B ---- */
    if (t == 1) {
        /* expand SOS into top-K beams; cand rows indexed by batch */
        for (int i = tid; i < BB * KK * TT; i += 512) {
            int pos = i & 63;
            int r = i >> 6;
            int b = r >> 2, k = r & 3;
            int tok1 = s_v[b * 4 + k];
            g_seqs[i] = (pos == 0) ? TOK_SOS : ((pos == 1) ? tok1 : TOK_PAD);
        }
        if (tid < 64) {
            int b = tid >> 2, k = tid & 3;
            int tok = s_v[b * 4 + k];
            g_scores[tid] = s_lp[b * 4 + k];
            g_fin[tid] = (tok == TOK_EOS) ? 1 : 0;
            g_last[tid] = tok;
        }
        return;
    }

    /* t >= 2: beam combine */
    for (int i = tid; i < BB * KK * TT; i += 512) sseq[i] = g_seqs[i];
    __syncthreads();
    if (tid < BB) {
        int b = tid;
        float tot[16];
        int tk[16];
        for (int k = 0; k < KK; k++) {
            int r = b * 4 + k;
            float sc = g_scores[r];
            int f = g_fin[r];
            for (int j = 0; j < KK; j++) {
                float lp = f ? ((j == 0) ? 0.f : NEGV) : s_lp[r * 4 + j];
                tot[k * 4 + j] = sc + lp;
                tk[k * 4 + j] = f ? TOK_PAD : s_v[r * 4 + j];
            }
        }
        for (int j = 0; j < KK; j++) {
            float bv = -FLT_MAX;
            int bi = 0;
            for (int c = 0; c < 16; c++)
                if (tot[c] > bv) { bv = tot[c]; bi = c; }   /* strict > => lowest idx on tie */
            snsc[b * 4 + j] = bv;
            sbid[b * 4 + j] = bi >> 2;
            stok[b * 4 + j] = tk[bi];
            tot[bi] = -FLT_MAX;
        }
    }
    __syncthreads();
    if (tid < 64) {
        int b = tid >> 2;
        snfin[tid] = g_fin[b * 4 + sbid[tid]] | ((stok[tid] == TOK_EOS) ? 1 : 0);
    }
    __syncthreads();
    if (tid < 64) {
        g_scores[tid] = snsc[tid];
        g_fin[tid] = snfin[tid];
        g_last[tid] = stok[tid];
    }
    for (int i = tid; i < BB * KK * TT; i += 512) {
        int b = i >> 8;
        int k = (i >> 6) & 3;
        int pos = i & 63;
        int src = sseq[b * 256 + sbid[b * 4 + k] * 64 + pos];
        g_seqs[i] = (pos == t) ? stok[b * 4 + k] : src;
    }
}

/* ------------------------------------------------------------------ */
/* kOut: pick best beam, write output                                  */
/* ------------------------------------------------------------------ */
__global__ void __launch_bounds__(64) kOut(float* out, int out_size) {
    __shared__ int best[16];
    int tid = threadIdx.x;
    if (tid < 16) {
        float bv = -FLT_MAX;
        int bi = 0;
        for (int k = 0; k < 4; k++) {
            float s = g_scores[tid * 4 + k];
            if (s > bv) { bv = s; bi = k; }   /* argmax: first max wins */
        }
        best[tid] = bi;
        if (out_size >= 1040) out[1024 + tid] = bv;
        else if (out_size < 1024 && out_size >= 16) out[tid] = bv;
    }
    __syncthreads();
    if (out_size >= 1024) {
        for (int i = tid; i < 1024; i += 64) {
            int b = i >> 6, pos = i & 63;
            out[i] = (float)g_seqs[b * 256 + best[b] * 64 + pos];
        }
    }
}

/* ------------------------------------------------------------------ */
extern "C" void kernel_launch(void* const* d_in, const int* in_sizes, int n_in,
                              void* d_out, int out_size) {
    const float* enc  = (const float*)d_in[0];
    const int*   lens = (const int*)d_in[1];
    const float* emb  = (const float*)d_in[2];
    const float* Wq   = (const float*)d_in[3];
    const float* Wk   = (const float*)d_in[4];
    const float* Wfc  = (const float*)d_in[5];
    const float* bfc  = (const float*)d_in[6];
    float* out = (float*)d_out;

    cudaFuncSetAttribute(kB, cudaFuncAttributeMaxDynamicSharedMemorySize, 65536);

    kWqk<<<dim3(32, 32), dim3(16, 16)>>>(Wq, Wk);
    kInit<<<1, 32>>>();

    /* step 1: decode from SOS, rows = batch index (M=16) */
    kQATT<<<16, 256>>>(enc, lens, emb, 16, 1);
    kB<<<dim3(NVB, 1), 256, 65536>>>(Wfc, bfc, 16);
    kFin<<<1, 512>>>(1, 16);

    /* steps 2..63: rows = b*4+k (M=64) */
    for (int t = 2; t < TT; t++) {
        kQATT<<<64, 256>>>(enc, lens, emb, 64, 4);
        kB<<<dim3(NVB, 2), 256, 65536>>>(Wfc, bfc, 64);
        kFin<<<1, 512>>>(t, 64);
    }

    kOut<<<1, 64>>>(out, out_size);
}